// round 1
// baseline (speedup 1.0000x reference)
#include <cuda_runtime.h>

#define BB 4
#define NSEC 1024
#define NPRIM 256
#define NNODES 1536
#define NH 4
#define OF 32
#define FG 128

// ---------------- scratch (static device memory, no allocs) ----------------
__device__ float g_scratch[4200000];

__device__ __forceinline__ float lrelu(float x) { return x > 0.f ? x : 0.2f * x; }
__device__ __forceinline__ float warpMax(float v) {
    #pragma unroll
    for (int o = 16; o > 0; o >>= 1) v = fmaxf(v, __shfl_xor_sync(0xffffffffu, v, o));
    return v;
}
__device__ __forceinline__ float warpSum(float v) {
    #pragma unroll
    for (int o = 16; o > 0; o >>= 1) v += __shfl_xor_sync(0xffffffffu, v, o);
    return v;
}

// ---------------- GEMM: C[M,N] = A[M,K] @ B[K,N] (+bias)(+relu) ------------
// 64x64 tile, BK=16, 256 threads, 4x4 per thread. Optional deterministic
// per-block partial sums (for the final ratio reduction).
__global__ void gemm_kernel(const float* __restrict__ A, const float* __restrict__ B,
                            const float* __restrict__ bias, float* __restrict__ C,
                            int M, int N, int K, int doRelu, float* __restrict__ part)
{
    __shared__ float As[16][64];
    __shared__ float Bs[16][64];
    int tid = threadIdx.x;
    int tx = tid & 15, ty = tid >> 4;
    int m0 = blockIdx.y * 64, n0 = blockIdx.x * 64;
    float acc[4][4] = {};
    int am = tid >> 2, ak = (tid & 3) << 2;
    int bk = tid >> 4, bn = (tid & 15) << 2;

    for (int k0 = 0; k0 < K; k0 += 16) {
        float4 a = *(const float4*)(A + (size_t)(m0 + am) * K + k0 + ak);
        As[ak + 0][am] = a.x; As[ak + 1][am] = a.y;
        As[ak + 2][am] = a.z; As[ak + 3][am] = a.w;
        *(float4*)&Bs[bk][bn] = *(const float4*)(B + (size_t)(k0 + bk) * N + n0 + bn);
        __syncthreads();
        #pragma unroll
        for (int k = 0; k < 16; k++) {
            float4 a4 = *(const float4*)&As[k][ty << 2];
            float4 b4 = *(const float4*)&Bs[k][tx << 2];
            float av[4] = {a4.x, a4.y, a4.z, a4.w};
            float bv[4] = {b4.x, b4.y, b4.z, b4.w};
            #pragma unroll
            for (int i = 0; i < 4; i++)
                #pragma unroll
                for (int j = 0; j < 4; j++)
                    acc[i][j] = fmaf(av[i], bv[j], acc[i][j]);
        }
        __syncthreads();
    }

    float bsum = 0.f;
    #pragma unroll
    for (int i = 0; i < 4; i++) {
        int row = m0 + (ty << 2) + i;
        #pragma unroll
        for (int j = 0; j < 4; j++) {
            int col = n0 + (tx << 2) + j;
            float v = acc[i][j];
            if (bias) v += bias[col];
            if (doRelu) v = fmaxf(v, 0.f);
            C[(size_t)row * N + col] = v;
            bsum += v;
        }
    }
    if (part) {
        __shared__ float red[256];
        red[tid] = bsum;
        __syncthreads();
        #pragma unroll
        for (int s = 128; s > 0; s >>= 1) {
            if (tid < s) red[tid] += red[tid + s];
            __syncthreads();
        }
        if (tid == 0) part[blockIdx.y * gridDim.x + blockIdx.x] = red[0];
    }
}

// ---------------- per-(b,n,h) attention scalars s,d ------------------------
__global__ void sd_kernel(const float* __restrict__ xp, const float* __restrict__ a_s,
                          const float* __restrict__ a_d, float* __restrict__ s,
                          float* __restrict__ d, int total)
{
    int idx = blockIdx.x * blockDim.x + threadIdx.x;
    if (idx >= total) return;
    int h = idx & 3;
    int bn = idx >> 2;
    const float* row = xp + (size_t)bn * FG + h * OF;
    const float* as_row = a_s + h * OF;
    const float* ad_row = a_d + h * OF;
    float ss = 0.f, dd = 0.f;
    #pragma unroll
    for (int f = 0; f < OF; f++) {
        float v = row[f];
        ss = fmaf(v, as_row[f], ss);
        dd = fmaf(v, ad_row[f], dd);
    }
    s[idx] = ss;
    d[idx] = dd;
}

// ---------------- sec-destination aggregation (layers 1 & 2) ---------------
// sources: 256 beam nodes + self. grid (16, H, B), 256 thr, warp per sec node
// (8 sec nodes sequentially per warp; 64 per block).
__global__ void sec_agg_kernel(const float* __restrict__ xp, const float* __restrict__ s,
                               const float* __restrict__ d, const float* __restrict__ bias,
                               float* __restrict__ out, int outStrideB)
{
    __shared__ float xpB[NPRIM * OF];  // 32KB: beam features for this head
    __shared__ float sB[NPRIM];
    int b = blockIdx.z, h = blockIdx.y;
    int i0 = blockIdx.x * 64;
    int tid = threadIdx.x, warp = tid >> 5, lane = tid & 31;
    const float* xpBatch = xp + (size_t)b * NNODES * FG;

    for (int idx = tid; idx < NPRIM * OF; idx += 256)
        xpB[idx] = xpBatch[(size_t)(NSEC + (idx >> 5)) * FG + h * OF + (idx & 31)];
    if (tid < NPRIM)
        sB[tid] = s[((size_t)b * NNODES + NSEC + tid) * NH + h];
    __syncthreads();

    float bval = bias[h * OF + lane];
    for (int r = 0; r < 8; r++) {
        int i = i0 + warp * 8 + r;
        float di = d[((size_t)b * NNODES + i) * NH + h];
        float si = s[((size_t)b * NNODES + i) * NH + h];
        float e[8];
        float m = -1e30f;
        #pragma unroll
        for (int r2 = 0; r2 < 8; r2++) {
            float x = lrelu(sB[lane + 32 * r2] + di);
            e[r2] = x;
            m = fmaxf(m, x);
        }
        m = warpMax(m);
        float es = lrelu(si + di);
        m = fmaxf(m, es);
        float w[8];
        float Zp = 0.f;
        #pragma unroll
        for (int r2 = 0; r2 < 8; r2++) { w[r2] = __expf(e[r2] - m); Zp += w[r2]; }
        Zp = warpSum(Zp);
        float ws = __expf(es - m);
        float Z = Zp + ws;
        float acc = ws * xpBatch[(size_t)i * FG + h * OF + lane];
        #pragma unroll
        for (int r2 = 0; r2 < 8; r2++) {
            #pragma unroll
            for (int l = 0; l < 32; l++) {
                float wv = __shfl_sync(0xffffffffu, w[r2], l);
                acc = fmaf(wv, xpB[(r2 * 32 + l) * OF + lane], acc);
            }
        }
        float v = acc / Z + bval;
        out[(size_t)b * outStrideB + (size_t)i * FG + h * OF + lane] = fmaxf(v, 0.f);
    }
}

// ---------------- beam-destination aggregation (layer 1 only) --------------
// sources: 1024 sec + prim_j + self. Online softmax over 4 chunks of 256.
// grid (32, H, B), 256 thr, warp per beam.
__global__ void beam_agg_kernel(const float* __restrict__ xp, const float* __restrict__ s,
                                const float* __restrict__ d, const float* __restrict__ bias,
                                float* __restrict__ out)
{
    __shared__ float xpS[256 * OF];
    __shared__ float sS[256];
    int b = blockIdx.z, h = blockIdx.y;
    int tid = threadIdx.x, warp = tid >> 5, lane = tid & 31;
    int j = blockIdx.x * 8 + warp;
    int nodeJ = NSEC + j;
    const float* xpBatch = xp + (size_t)b * NNODES * FG;

    float dj = d[((size_t)b * NNODES + nodeJ) * NH + h];
    float m = -1e30f, Z = 0.f, acc = 0.f;

    for (int c = 0; c < 4; c++) {
        __syncthreads();
        for (int idx = tid; idx < 256 * OF; idx += 256)
            xpS[idx] = xpBatch[(size_t)(c * 256 + (idx >> 5)) * FG + h * OF + (idx & 31)];
        if (tid < 256)
            sS[tid] = s[((size_t)b * NNODES + c * 256 + tid) * NH + h];
        __syncthreads();

        float e[8];
        float mc = -1e30f;
        #pragma unroll
        for (int r2 = 0; r2 < 8; r2++) {
            float x = lrelu(sS[lane + 32 * r2] + dj);
            e[r2] = x;
            mc = fmaxf(mc, x);
        }
        mc = warpMax(mc);
        float mn = fmaxf(m, mc);
        float sc = __expf(m - mn);
        Z *= sc;
        acc *= sc;
        m = mn;
        float w[8];
        float Zp = 0.f;
        #pragma unroll
        for (int r2 = 0; r2 < 8; r2++) { w[r2] = __expf(e[r2] - m); Zp += w[r2]; }
        Zp = warpSum(Zp);
        Z += Zp;
        #pragma unroll
        for (int r2 = 0; r2 < 8; r2++) {
            #pragma unroll
            for (int l = 0; l < 32; l++) {
                float wv = __shfl_sync(0xffffffffu, w[r2], l);
                acc = fmaf(wv, xpS[(r2 * 32 + l) * OF + lane], acc);
            }
        }
    }

    // prim_j source + self loop
    float sp = s[((size_t)b * NNODES + NSEC + NPRIM + j) * NH + h];
    float sb = s[((size_t)b * NNODES + nodeJ) * NH + h];
    float ep = lrelu(sp + dj);
    float eself = lrelu(sb + dj);
    float mn = fmaxf(m, fmaxf(ep, eself));
    float sc = __expf(m - mn);
    Z *= sc;
    acc *= sc;
    float wp = __expf(ep - mn);
    float ws = __expf(eself - mn);
    Z += wp + ws;
    acc = fmaf(wp, xpBatch[(size_t)(NSEC + NPRIM + j) * FG + h * OF + lane], acc);
    acc = fmaf(ws, xpBatch[(size_t)nodeJ * FG + h * OF + lane], acc);

    float v = acc / Z + bias[h * OF + lane];
    out[(size_t)b * NNODES * FG + (size_t)nodeJ * FG + h * OF + lane] = fmaxf(v, 0.f);
}

// ---------------- ratio + scale/threshold ----------------------------------
__global__ void ratio_kernel(const float* __restrict__ pP, const float* __restrict__ pT,
                             const float* __restrict__ part, float* __restrict__ ratio)
{
    int warp = threadIdx.x >> 5, lane = threadIdx.x & 31;
    if (warp >= BB) return;
    float ps = part[warp * 64 + lane] + part[warp * 64 + 32 + lane];
    ps = warpSum(ps);
    float pps = 0.f;
    #pragma unroll
    for (int k = 0; k < 8; k++) pps += pP[warp * 256 + lane + 32 * k];
    pps = warpSum(pps);
    if (lane == 0) {
        float num = fmaxf((*pT) - pps, 0.f);
        float r = num / (ps + 1e-5f);
        ratio[warp] = fminf(r, 1.f);
    }
}

__global__ void scale_kernel(float* __restrict__ C, const float* __restrict__ ratio)
{
    int idx = blockIdx.x * 256 + threadIdx.x;
    int b = idx >> 18;  // 1024*256 elems per batch
    float v = C[idx] * ratio[b];
    C[idx] = (v > 0.001f) ? v : 0.f;
}

// ---------------- launch ----------------------------------------------------
extern "C" void kernel_launch(void* const* d_in, const int* in_sizes, int n_in,
                              void* d_out, int out_size)
{
    const float* h   = (const float*)d_in[0];
    const float* pP  = (const float*)d_in[1];
    const float* pT  = (const float*)d_in[2];
    const float* W0  = (const float*)d_in[3];
    const float* b0  = (const float*)d_in[4];
    const float* as0 = (const float*)d_in[5];
    const float* ad0 = (const float*)d_in[6];
    const float* W1  = (const float*)d_in[7];
    const float* b1  = (const float*)d_in[8];
    const float* as1 = (const float*)d_in[9];
    const float* ad1 = (const float*)d_in[10];
    const float* Wf0 = (const float*)d_in[11];
    const float* bf0 = (const float*)d_in[12];
    const float* Wf1 = (const float*)d_in[13];
    const float* bf1 = (const float*)d_in[14];
    float* out = (float*)d_out;

    float* base = nullptr;
    cudaGetSymbolAddress((void**)&base, g_scratch);
    float* xp1  = base;
    float* x1   = xp1 + 786432;
    float* xp2  = x1 + 786432;
    float* hg   = xp2 + 786432;
    float* z    = hg + 524288;
    float* s1   = z + 1048576;
    float* d1   = s1 + 24576;
    float* s2   = d1 + 24576;
    float* d2   = s2 + 24576;
    float* part = d2 + 24576;
    float* ratio = part + 256;

    // Layer 1
    gemm_kernel<<<dim3(2, 96), 256>>>(h, W0, nullptr, xp1, BB * NNODES, FG, FG, 0, nullptr);
    sd_kernel<<<96, 256>>>(xp1, as0, ad0, s1, d1, BB * NNODES * NH);
    sec_agg_kernel<<<dim3(16, NH, BB), 256>>>(xp1, s1, d1, b0, x1, NNODES * FG);
    beam_agg_kernel<<<dim3(32, NH, BB), 256>>>(xp1, s1, d1, b0, x1);

    // Layer 2 (only sec destinations needed downstream)
    gemm_kernel<<<dim3(2, 96), 256>>>(x1, W1, nullptr, xp2, BB * NNODES, FG, FG, 0, nullptr);
    sd_kernel<<<96, 256>>>(xp2, as1, ad1, s2, d2, BB * NNODES * NH);
    sec_agg_kernel<<<dim3(16, NH, BB), 256>>>(xp2, s2, d2, b1, hg, NSEC * FG);

    // FC stack
    gemm_kernel<<<dim3(4, 64), 256>>>(hg, Wf0, bf0, z, BB * NSEC, 256, FG, 1, nullptr);
    gemm_kernel<<<dim3(4, 64), 256>>>(z, Wf1, bf1, out, BB * NSEC, 256, 256, 1, part);

    // Power ratio + threshold
    ratio_kernel<<<1, 128>>>(pP, pT, part, ratio);
    scale_kernel<<<4096, 256>>>(out, ratio);
}

// round 2
// speedup vs baseline: 1.4724x; 1.4724x over previous
#include <cuda_runtime.h>

#define BB 4
#define NSEC 1024
#define NPRIM 256
#define NNODES 1536
#define NH 4
#define OF 32
#define FG 128

// ---------------- scratch (static device memory, no allocs) ----------------
__device__ float g_scratch[4700000];

__device__ __forceinline__ float lrelu(float x) { return x > 0.f ? x : 0.2f * x; }
__device__ __forceinline__ float warpSum(float v) {
    #pragma unroll
    for (int o = 16; o > 0; o >>= 1) v += __shfl_xor_sync(0xffffffffu, v, o);
    return v;
}

// ---------------- GEMM: C[M,N] = A[M,K] @ B[K,N] (+bias)(+relu) ------------
__global__ void gemm_kernel(const float* __restrict__ A, const float* __restrict__ B,
                            const float* __restrict__ bias, float* __restrict__ C,
                            int M, int N, int K, int doRelu, float* __restrict__ part)
{
    __shared__ float As[16][64];
    __shared__ float Bs[16][64];
    int tid = threadIdx.x;
    int tx = tid & 15, ty = tid >> 4;
    int m0 = blockIdx.y * 64, n0 = blockIdx.x * 64;
    float acc[4][4] = {};
    int am = tid >> 2, ak = (tid & 3) << 2;
    int bk = tid >> 4, bn = (tid & 15) << 2;

    for (int k0 = 0; k0 < K; k0 += 16) {
        float4 a = *(const float4*)(A + (size_t)(m0 + am) * K + k0 + ak);
        As[ak + 0][am] = a.x; As[ak + 1][am] = a.y;
        As[ak + 2][am] = a.z; As[ak + 3][am] = a.w;
        *(float4*)&Bs[bk][bn] = *(const float4*)(B + (size_t)(k0 + bk) * N + n0 + bn);
        __syncthreads();
        #pragma unroll
        for (int k = 0; k < 16; k++) {
            float4 a4 = *(const float4*)&As[k][ty << 2];
            float4 b4 = *(const float4*)&Bs[k][tx << 2];
            float av[4] = {a4.x, a4.y, a4.z, a4.w};
            float bv[4] = {b4.x, b4.y, b4.z, b4.w};
            #pragma unroll
            for (int i = 0; i < 4; i++)
                #pragma unroll
                for (int j = 0; j < 4; j++)
                    acc[i][j] = fmaf(av[i], bv[j], acc[i][j]);
        }
        __syncthreads();
    }

    float bsum = 0.f;
    #pragma unroll
    for (int i = 0; i < 4; i++) {
        int row = m0 + (ty << 2) + i;
        #pragma unroll
        for (int j = 0; j < 4; j++) {
            int col = n0 + (tx << 2) + j;
            float v = acc[i][j];
            if (bias) v += bias[col];
            if (doRelu) v = fmaxf(v, 0.f);
            C[(size_t)row * N + col] = v;
            bsum += v;
        }
    }
    if (part) {
        __shared__ float red[256];
        red[tid] = bsum;
        __syncthreads();
        #pragma unroll
        for (int s = 128; s > 0; s >>= 1) {
            if (tid < s) red[tid] += red[tid + s];
            __syncthreads();
        }
        if (tid == 0) part[blockIdx.y * gridDim.x + blockIdx.x] = red[0];
    }
}

// ---------------- per-(bh,n) attention scalars s,d (bh-major layout) -------
__global__ void sd_kernel(const float* __restrict__ xp, const float* __restrict__ a_s,
                          const float* __restrict__ a_d, float* __restrict__ s,
                          float* __restrict__ d)
{
    int idx = blockIdx.x * 256 + threadIdx.x;   // over B*NH*NNODES = 24576
    int bh = idx / NNODES;
    int n = idx - bh * NNODES;
    int b = bh >> 2, h = bh & 3;
    const float* row = xp + ((size_t)(b * NNODES + n)) * FG + h * OF;
    const float* as_row = a_s + h * OF;
    const float* ad_row = a_d + h * OF;
    float ss = 0.f, dd = 0.f;
    #pragma unroll
    for (int f = 0; f < OF; f += 4) {
        float4 v = *(const float4*)&row[f];
        float4 av = *(const float4*)&as_row[f];
        float4 dv = *(const float4*)&ad_row[f];
        ss = fmaf(v.x, av.x, fmaf(v.y, av.y, fmaf(v.z, av.z, fmaf(v.w, av.w, ss))));
        dd = fmaf(v.x, dv.x, fmaf(v.y, dv.y, fmaf(v.z, dv.z, fmaf(v.w, dv.w, dd))));
    }
    s[idx] = ss;
    d[idx] = dd;
}

// ---------------- segment max of s over sec range & beam range -------------
__global__ void smax_kernel(const float* __restrict__ s, float* __restrict__ smax)
{
    __shared__ float red[256];
    int bh = blockIdx.x, tid = threadIdx.x;
    const float* sRow = s + (size_t)bh * NNODES;
    float m = fmaxf(fmaxf(sRow[tid], sRow[tid + 256]),
                    fmaxf(sRow[tid + 512], sRow[tid + 768]));
    red[tid] = m;
    __syncthreads();
    #pragma unroll
    for (int st = 128; st > 0; st >>= 1) {
        if (tid < st) red[tid] = fmaxf(red[tid], red[tid + st]);
        __syncthreads();
    }
    if (tid == 0) smax[bh * 2] = red[0];
    __syncthreads();
    red[tid] = sRow[NSEC + tid];
    __syncthreads();
    #pragma unroll
    for (int st = 128; st > 0; st >>= 1) {
        if (tid < st) red[tid] = fmaxf(red[tid], red[tid + st]);
        __syncthreads();
    }
    if (tid == 0) smax[bh * 2 + 1] = red[0];
}

// ---------------- sec-destination aggregation (GEMM-style, single pass) ----
// 64 dst x 32 feat tile per block, 256 srcs (beams) + self. grid (16, 16bh).
__global__ void sec_agg2_kernel(const float* __restrict__ xp, const float* __restrict__ s,
                                const float* __restrict__ d, const float* __restrict__ smax,
                                const float* __restrict__ bias, float* __restrict__ out,
                                int outStrideB)
{
    __shared__ float xS[32 * 32];
    __shared__ float wS[64 * 33];
    __shared__ float sS[32];
    __shared__ float dS[64], mS[64], zS[64];
    int tid = threadIdx.x;
    int bh = blockIdx.y;
    int b = bh >> 2, h = bh & 3;
    int dst0 = blockIdx.x * 64;
    const float* sRow = s + (size_t)bh * NNODES;
    const float* dRow = d + (size_t)bh * NNODES;
    const float* xpB = xp + (size_t)b * NNODES * FG + h * OF;

    if (tid < 64) {
        int i = dst0 + tid;
        float dv = dRow[i];
        dS[tid] = dv;
        mS[tid] = lrelu(fmaxf(smax[bh * 2 + 1], sRow[i]) + dv);
    }
    int txf = tid & 7, tyd = tid >> 3;
    int ssrc = tid & 31, dgrp = tid >> 5;
    float acc[2][4] = {};
    float zacc[2] = {0.f, 0.f};

    for (int c = 0; c < 8; c++) {
        __syncthreads();
        #pragma unroll
        for (int q = 0; q < 4; q++) {
            int idx = tid + q * 256;
            xS[idx] = xpB[(size_t)(NSEC + c * 32 + (idx >> 5)) * FG + (idx & 31)];
        }
        if (tid < 32) sS[tid] = sRow[NSEC + c * 32 + tid];
        __syncthreads();
        float sv = sS[ssrc];
        #pragma unroll
        for (int r = 0; r < 8; r++) {
            int dd = dgrp * 8 + r;
            wS[dd * 33 + ssrc] = __expf(lrelu(sv + dS[dd]) - mS[dd]);
        }
        __syncthreads();
        #pragma unroll 8
        for (int k = 0; k < 32; k++) {
            float w0 = wS[(2 * tyd) * 33 + k];
            float w1 = wS[(2 * tyd + 1) * 33 + k];
            float4 x = *(const float4*)&xS[k * 32 + 4 * txf];
            acc[0][0] = fmaf(w0, x.x, acc[0][0]);
            acc[0][1] = fmaf(w0, x.y, acc[0][1]);
            acc[0][2] = fmaf(w0, x.z, acc[0][2]);
            acc[0][3] = fmaf(w0, x.w, acc[0][3]);
            acc[1][0] = fmaf(w1, x.x, acc[1][0]);
            acc[1][1] = fmaf(w1, x.y, acc[1][1]);
            acc[1][2] = fmaf(w1, x.z, acc[1][2]);
            acc[1][3] = fmaf(w1, x.w, acc[1][3]);
            if (txf == 0) { zacc[0] += w0; zacc[1] += w1; }
        }
    }
    __syncthreads();
    if (txf == 0) { zS[2 * tyd] = zacc[0]; zS[2 * tyd + 1] = zacc[1]; }
    __syncthreads();
    float4 bv = *(const float4*)&bias[h * OF + 4 * txf];
    #pragma unroll
    for (int r = 0; r < 2; r++) {
        int i = dst0 + 2 * tyd + r;
        float dv = dS[2 * tyd + r], m = mS[2 * tyd + r];
        float ws = __expf(lrelu(sRow[i] + dv) - m);
        float4 xs = *(const float4*)&xpB[(size_t)i * FG + 4 * txf];
        float inv = 1.f / (zS[2 * tyd + r] + ws);
        float4 o;
        o.x = fmaxf(fmaf(ws, xs.x, acc[r][0]) * inv + bv.x, 0.f);
        o.y = fmaxf(fmaf(ws, xs.y, acc[r][1]) * inv + bv.y, 0.f);
        o.z = fmaxf(fmaf(ws, xs.z, acc[r][2]) * inv + bv.z, 0.f);
        o.w = fmaxf(fmaf(ws, xs.w, acc[r][3]) * inv + bv.w, 0.f);
        *(float4*)&out[(size_t)b * outStrideB + (size_t)i * FG + h * OF + 4 * txf] = o;
    }
}

// ---------------- beam-destination aggregation, k-split partial pass -------
// 64 dst x 32 feat tile, 256 of 1024 sec srcs per block. grid (4, 4kblk, 16bh).
__global__ void beam_agg_part_kernel(const float* __restrict__ xp, const float* __restrict__ s,
                                     const float* __restrict__ d, const float* __restrict__ smax,
                                     float* __restrict__ pfeat, float* __restrict__ pZ)
{
    __shared__ float xS[32 * 32];
    __shared__ float wS[64 * 33];
    __shared__ float sS[32];
    __shared__ float dS[64], mS[64];
    int tid = threadIdx.x;
    int bh = blockIdx.z;
    int b = bh >> 2, h = bh & 3;
    int dst0 = blockIdx.x * 64;
    int kblk = blockIdx.y;
    const float* sRow = s + (size_t)bh * NNODES;
    const float* dRow = d + (size_t)bh * NNODES;
    const float* xpB = xp + (size_t)b * NNODES * FG + h * OF;

    if (tid < 64) {
        int j = dst0 + tid;
        float dv = dRow[NSEC + j];
        dS[tid] = dv;
        float sP = sRow[NSEC + NPRIM + j];
        float sB = sRow[NSEC + j];
        mS[tid] = lrelu(fmaxf(fmaxf(smax[bh * 2], sP), sB) + dv);
    }
    int txf = tid & 7, tyd = tid >> 3;
    int ssrc = tid & 31, dgrp = tid >> 5;
    float acc[2][4] = {};
    float zacc[2] = {0.f, 0.f};

    for (int c = 0; c < 8; c++) {
        __syncthreads();
        #pragma unroll
        for (int q = 0; q < 4; q++) {
            int idx = tid + q * 256;
            xS[idx] = xpB[(size_t)(kblk * 256 + c * 32 + (idx >> 5)) * FG + (idx & 31)];
        }
        if (tid < 32) sS[tid] = sRow[kblk * 256 + c * 32 + tid];
        __syncthreads();
        float sv = sS[ssrc];
        #pragma unroll
        for (int r = 0; r < 8; r++) {
            int dd = dgrp * 8 + r;
            wS[dd * 33 + ssrc] = __expf(lrelu(sv + dS[dd]) - mS[dd]);
        }
        __syncthreads();
        #pragma unroll 8
        for (int k = 0; k < 32; k++) {
            float w0 = wS[(2 * tyd) * 33 + k];
            float w1 = wS[(2 * tyd + 1) * 33 + k];
            float4 x = *(const float4*)&xS[k * 32 + 4 * txf];
            acc[0][0] = fmaf(w0, x.x, acc[0][0]);
            acc[0][1] = fmaf(w0, x.y, acc[0][1]);
            acc[0][2] = fmaf(w0, x.z, acc[0][2]);
            acc[0][3] = fmaf(w0, x.w, acc[0][3]);
            acc[1][0] = fmaf(w1, x.x, acc[1][0]);
            acc[1][1] = fmaf(w1, x.y, acc[1][1]);
            acc[1][2] = fmaf(w1, x.z, acc[1][2]);
            acc[1][3] = fmaf(w1, x.w, acc[1][3]);
            if (txf == 0) { zacc[0] += w0; zacc[1] += w1; }
        }
    }
    size_t pbase = (size_t)(bh * 4 + kblk) * 256;
    #pragma unroll
    for (int r = 0; r < 2; r++) {
        int j = dst0 + 2 * tyd + r;
        float4 o = {acc[r][0], acc[r][1], acc[r][2], acc[r][3]};
        *(float4*)&pfeat[(pbase + j) * 32 + 4 * txf] = o;
        if (txf == 0) pZ[pbase + j] = zacc[r];
    }
}

// ---------------- beam combine (fixed-order deterministic) -----------------
__global__ void beam_combine_kernel(const float* __restrict__ xp, const float* __restrict__ s,
                                    const float* __restrict__ d, const float* __restrict__ smax,
                                    const float* __restrict__ pfeat, const float* __restrict__ pZ,
                                    const float* __restrict__ bias, float* __restrict__ out)
{
    int tid = threadIdx.x, warp = tid >> 5, lane = tid & 31;
    int bh = blockIdx.y, b = bh >> 2, h = bh & 3;
    int j = blockIdx.x * 8 + warp;
    const float* sRow = s + (size_t)bh * NNODES;
    const float* dRow = d + (size_t)bh * NNODES;
    float dv = dRow[NSEC + j];
    float sP = sRow[NSEC + NPRIM + j];
    float sB = sRow[NSEC + j];
    float m = lrelu(fmaxf(fmaxf(smax[bh * 2], sP), sB) + dv);   // identical to partial pass
    float wp = __expf(lrelu(sP + dv) - m);
    float ws = __expf(lrelu(sB + dv) - m);
    size_t p0 = (size_t)bh * 4 * 256 + j;
    float Z = ((pZ[p0] + pZ[p0 + 256]) + pZ[p0 + 512]) + pZ[p0 + 768] + wp + ws;
    float acc = ((pfeat[p0 * 32 + lane] + pfeat[(p0 + 256) * 32 + lane])
                 + pfeat[(p0 + 512) * 32 + lane]) + pfeat[(p0 + 768) * 32 + lane];
    const float* xpB = xp + (size_t)b * NNODES * FG + h * OF;
    acc = fmaf(wp, xpB[(size_t)(NSEC + NPRIM + j) * FG + lane], acc);
    acc = fmaf(ws, xpB[(size_t)(NSEC + j) * FG + lane], acc);
    float v = acc / Z + bias[h * OF + lane];
    out[(size_t)b * NNODES * FG + (size_t)(NSEC + j) * FG + h * OF + lane] = fmaxf(v, 0.f);
}

// ---------------- ratio + scale/threshold ----------------------------------
__global__ void ratio_kernel(const float* __restrict__ pP, const float* __restrict__ pT,
                             const float* __restrict__ part, float* __restrict__ ratio)
{
    int warp = threadIdx.x >> 5, lane = threadIdx.x & 31;
    if (warp >= BB) return;
    float ps = part[warp * 64 + lane] + part[warp * 64 + 32 + lane];
    ps = warpSum(ps);
    float pps = 0.f;
    #pragma unroll
    for (int k = 0; k < 8; k++) pps += pP[warp * 256 + lane + 32 * k];
    pps = warpSum(pps);
    if (lane == 0) {
        float num = fmaxf((*pT) - pps, 0.f);
        float r = num / (ps + 1e-5f);
        ratio[warp] = fminf(r, 1.f);
    }
}

__global__ void scale_kernel(float* __restrict__ C, const float* __restrict__ ratio)
{
    int idx = blockIdx.x * 256 + threadIdx.x;
    int b = idx >> 18;
    float v = C[idx] * ratio[b];
    C[idx] = (v > 0.001f) ? v : 0.f;
}

// ---------------- launch ----------------------------------------------------
extern "C" void kernel_launch(void* const* d_in, const int* in_sizes, int n_in,
                              void* d_out, int out_size)
{
    const float* h   = (const float*)d_in[0];
    const float* pP  = (const float*)d_in[1];
    const float* pT  = (const float*)d_in[2];
    const float* W0  = (const float*)d_in[3];
    const float* b0  = (const float*)d_in[4];
    const float* as0 = (const float*)d_in[5];
    const float* ad0 = (const float*)d_in[6];
    const float* W1  = (const float*)d_in[7];
    const float* b1  = (const float*)d_in[8];
    const float* as1 = (const float*)d_in[9];
    const float* ad1 = (const float*)d_in[10];
    const float* Wf0 = (const float*)d_in[11];
    const float* bf0 = (const float*)d_in[12];
    const float* Wf1 = (const float*)d_in[13];
    const float* bf1 = (const float*)d_in[14];
    float* out = (float*)d_out;

    float* base = nullptr;
    cudaGetSymbolAddress((void**)&base, g_scratch);
    float* xp1   = base;                 // 786432
    float* x1    = xp1 + 786432;         // 786432
    float* xp2   = x1 + 786432;          // 786432
    float* hg    = xp2 + 786432;         // 524288
    float* z     = hg + 524288;          // 1048576
    float* s1    = z + 1048576;          // 24576
    float* d1    = s1 + 24576;
    float* s2    = d1 + 24576;
    float* d2    = s2 + 24576;
    float* smax1 = d2 + 24576;           // 32
    float* smax2 = smax1 + 32;           // 32
    float* pfeat = smax2 + 32;           // 524288
    float* pZ    = pfeat + 524288;       // 16384
    float* part  = pZ + 16384;           // 256
    float* ratio = part + 256;           // 4

    // Layer 1
    gemm_kernel<<<dim3(2, 96), 256>>>(h, W0, nullptr, xp1, BB * NNODES, FG, FG, 0, nullptr);
    sd_kernel<<<96, 256>>>(xp1, as0, ad0, s1, d1);
    smax_kernel<<<16, 256>>>(s1, smax1);
    sec_agg2_kernel<<<dim3(16, 16), 256>>>(xp1, s1, d1, smax1, b0, x1, NNODES * FG);
    beam_agg_part_kernel<<<dim3(4, 4, 16), 256>>>(xp1, s1, d1, smax1, pfeat, pZ);
    beam_combine_kernel<<<dim3(32, 16), 256>>>(xp1, s1, d1, smax1, pfeat, pZ, b0, x1);

    // Layer 2 (only sec destinations needed downstream)
    gemm_kernel<<<dim3(2, 96), 256>>>(x1, W1, nullptr, xp2, BB * NNODES, FG, FG, 0, nullptr);
    sd_kernel<<<96, 256>>>(xp2, as1, ad1, s2, d2);
    smax_kernel<<<16, 256>>>(s2, smax2);
    sec_agg2_kernel<<<dim3(16, 16), 256>>>(xp2, s2, d2, smax2, b1, hg, NSEC * FG);

    // FC stack
    gemm_kernel<<<dim3(4, 64), 256>>>(hg, Wf0, bf0, z, BB * NSEC, 256, FG, 1, nullptr);
    gemm_kernel<<<dim3(4, 64), 256>>>(z, Wf1, bf1, out, BB * NSEC, 256, 256, 1, part);

    // Power ratio + threshold
    ratio_kernel<<<1, 128>>>(pP, pT, part, ratio);
    scale_kernel<<<4096, 256>>>(out, ratio);
}